// round 5
// baseline (speedup 1.0000x reference)
#include <cuda_runtime.h>
#include <cuda_bf16.h>
#include <math.h>

// Problem shapes (fixed for this dataset entry)
#define B_   128
#define N_   8
#define LQ_  32
#define LD_  256
#define D_   128
#define KT_  128          // k-rows per smem tile (2 tiles of 128 = LD)
#define DSTRIDE 132       // padded row stride (floats): conflict-free per 8-lane phase
#define NEGV (-9999.0f)
#define EPSV (1e-12f)

#define NT_  128          // threads per block (4 warps)

// scores[tensor][b][n]  (tensor 0 = student/cq, 1 = teacher/orig)
__device__ float g_scores[2 * B_ * N_];

// Shared memory (floats): d tile + q tile + row norms + per-warp partial sums
#define SMEM_FLOATS (KT_ * DSTRIDE + LQ_ * D_ + KT_ + 8)
#define SMEM_BYTES  (SMEM_FLOATS * 4)

// Packed dual-fp32 FMA (sm_100+): acc.lo += a.lo*b.lo; acc.hi += a.hi*b.hi
#define FMA_F32X2(acc, a, b) \
    asm("fma.rn.f32x2 %0, %1, %2, %3;" : "=l"(acc) : "l"(a), "l"(b), "l"(acc))

__device__ __forceinline__ float f32x2_hsum(unsigned long long p) {
    unsigned int lo, hi;
    asm("mov.b64 {%0, %1}, %2;" : "=r"(lo), "=r"(hi) : "l"(p));
    return __uint_as_float(lo) + __uint_as_float(hi);
}

__global__ __launch_bounds__(NT_, 2)
void maxsim_kernel(const float* __restrict__ q_reps,
                   const float* __restrict__ d_cq,
                   const float* __restrict__ d_orig,
                   const int*   __restrict__ d_mask)
{
    extern __shared__ float sm[];
    float* d_s  = sm;                        // [KT_][DSTRIDE]
    float* q_s  = d_s + KT_ * DSTRIDE;       // [LQ_][D_]
    float* nrm  = q_s + LQ_ * D_;            // [KT_]
    float* wsum = nrm + KT_;                 // [4]

    const int bid    = blockIdx.x;
    const int tensor = bid >> 10;            // / (N_*B_) = /1024
    const int rem    = bid & 1023;
    const int b      = rem >> 3;             // / N_
    const int n      = rem & 7;              // % N_

    const float* dptr = (tensor ? d_orig : d_cq)
                        + ((size_t)(n * B_ + b)) * (size_t)(LD_ * D_);
    const int*   mptr = d_mask + (n * B_ + b) * LD_;

    const int t  = threadIdx.x;
    const int tx = t & 31;                    // lane
    const int ty = t >> 5;                    // warp id (0..3) == q-group

    // ---- load q[b] into smem (coalesced float4) ----
    {
        const float4* qb = (const float4*)(q_reps + (size_t)b * LQ_ * D_);
        float4* qs4 = (float4*)q_s;
        #pragma unroll
        for (int i = t; i < LQ_ * D_ / 4; i += NT_) qs4[i] = qb[i];
    }
    __syncthreads();

    // ---- normalize q rows in smem: warp ty handles rows ty*8 .. ty*8+7 ----
    #pragma unroll
    for (int r = ty * 8; r < ty * 8 + 8; ++r) {
        float4 v = ((float4*)(q_s + r * D_))[tx];
        float ss = v.x * v.x + v.y * v.y + v.z * v.z + v.w * v.w;
        #pragma unroll
        for (int o = 16; o; o >>= 1) ss += __shfl_xor_sync(0xffffffffu, ss, o);
        float inv = 1.0f / fmaxf(sqrtf(ss), EPSV);
        v.x *= inv; v.y *= inv; v.z *= inv; v.w *= inv;
        ((float4*)(q_s + r * D_))[tx] = v;
    }
    __syncthreads();

    // running max over ALL of Ld for this thread's 8 q-rows
    // (each warp covers every k-col of a tile: 32 lanes x 4 cols)
    float maxv[8];
    #pragma unroll
    for (int qi = 0; qi < 8; ++qi) maxv[qi] = NEGV;

    // ---- two k-tiles of 128 rows ----
    #pragma unroll
    for (int kt = 0; kt < LD_ / KT_; ++kt) {
        const float* dbase = dptr + (size_t)kt * KT_ * D_;

        // masks for this thread's 4 k-cols (tx + 32j)
        int mreg[4];
        #pragma unroll
        for (int j = 0; j < 4; ++j) mreg[j] = mptr[kt * KT_ + tx + 32 * j];

        // load tile (coalesced LDG.128, conflict-free STS.128)
        {
            const float4* dg = (const float4*)dbase;
            #pragma unroll
            for (int i = t; i < KT_ * (D_ / 4); i += NT_) {
                int k = i >> 5;               // / (D_/4)
                int c = i & 31;
                float4 v = dg[i];
                *(float4*)(d_s + k * DSTRIDE + 4 * c) = v;
            }
        }
        __syncthreads();

        // per-row L2 norms (one row per thread, conflict-free float4 reads)
        {
            float ss = 0.f;
            const float* row = d_s + t * DSTRIDE;
            #pragma unroll
            for (int c = 0; c < D_ / 4; ++c) {
                float4 v = *(const float4*)(row + 4 * c);
                ss += v.x * v.x + v.y * v.y + v.z * v.z + v.w * v.w;
            }
            nrm[t] = fmaxf(sqrtf(ss), EPSV);
        }
        __syncthreads();

        // register-blocked GEMM: 8 q-rows x 4 k-cols per thread.
        // Per step: 4 divergent d-LDS.128 (16 crossbar-cyc) + 8 broadcast
        // q-LDS (~8 cyc) vs 64 FMA2 (32 SM-issue-cyc) -> FMA-bound at ~75%.
        unsigned long long acc2[8][4];
        #pragma unroll
        for (int qi = 0; qi < 8; ++qi)
            #pragma unroll
            for (int j = 0; j < 4; ++j) acc2[qi][j] = 0ULL;

        const float* qbase = q_s + ty * 8 * D_;

        #pragma unroll 4
        for (int dd = 0; dd < D_; dd += 4) {
            ulonglong2 dv[4];
            #pragma unroll
            for (int j = 0; j < 4; ++j)
                dv[j] = *(const ulonglong2*)(d_s + (tx + 32 * j) * DSTRIDE + dd);
            #pragma unroll
            for (int qi = 0; qi < 8; ++qi) {
                ulonglong2 qv = *(const ulonglong2*)(qbase + qi * D_ + dd);
                #pragma unroll
                for (int j = 0; j < 4; ++j) {
                    FMA_F32X2(acc2[qi][j], qv.x, dv[j].x);
                    FMA_F32X2(acc2[qi][j], qv.y, dv[j].y);
                }
            }
        }

        // epilogue: hsum packed halves, scale by 1/norm, mask, running max
        #pragma unroll
        for (int j = 0; j < 4; ++j) {
            if (mreg[j]) {
                float inv = 1.0f / nrm[tx + 32 * j];
                #pragma unroll
                for (int qi = 0; qi < 8; ++qi)
                    maxv[qi] = fmaxf(maxv[qi], f32x2_hsum(acc2[qi][j]) * inv);
            }
        }
        __syncthreads();   // before next tile overwrites d_s / nrm
    }

    // ---- lane-max: each warp covered all 256 k-cols, so this completes
    //      the per-q-row max; then sum the warp's 8 q-rows ----
    #pragma unroll
    for (int qi = 0; qi < 8; ++qi)
        #pragma unroll
        for (int o = 16; o; o >>= 1)
            maxv[qi] = fmaxf(maxv[qi], __shfl_xor_sync(0xffffffffu, maxv[qi], o));

    if (tx == 0) {
        float s = 0.f;
        #pragma unroll
        for (int qi = 0; qi < 8; ++qi) s += maxv[qi];
        wsum[ty] = s;
    }
    __syncthreads();
    if (t == 0) {
        float s = wsum[0] + wsum[1] + wsum[2] + wsum[3];
        g_scores[tensor * (B_ * N_) + b * N_ + n] = s;
    }
}

__global__ void loss_kernel(float* __restrict__ out)
{
    __shared__ float part[B_];
    const int b = threadIdx.x;   // 128 threads, one per batch row

    const float* ss = g_scores + b * N_;            // student
    const float* ts = g_scores + B_ * N_ + b * N_;  // teacher

    float sv[N_], tv[N_];
    float ms = -INFINITY, mt = -INFINITY;
    #pragma unroll
    for (int j = 0; j < N_; ++j) {
        sv[j] = ss[j]; tv[j] = ts[j];
        ms = fmaxf(ms, sv[j]); mt = fmaxf(mt, tv[j]);
    }
    float es = 0.f, et = 0.f;
    #pragma unroll
    for (int j = 0; j < N_; ++j) {
        es += expf(sv[j] - ms);
        et += expf(tv[j] - mt);
    }
    float lse_s = ms + logf(es);
    float lse_t = mt + logf(et);

    float lb = 0.f;
    #pragma unroll
    for (int j = 0; j < N_; ++j) {
        float lt = tv[j] - lse_t;
        float ls = sv[j] - lse_s;
        lb += expf(lt) * (lt - ls);
    }
    part[b] = lb;
    __syncthreads();

    // tree reduction over 128 threads
    for (int s = 64; s > 0; s >>= 1) {
        if (b < s) part[b] += part[b + s];
        __syncthreads();
    }
    if (b == 0) out[0] = part[0] / (float)B_;
}

extern "C" void kernel_launch(void* const* d_in, const int* in_sizes, int n_in,
                              void* d_out, int out_size)
{
    const float* q_reps = (const float*)d_in[0];
    const float* d_cq   = (const float*)d_in[1];
    const float* d_orig = (const float*)d_in[2];
    const int*   d_mask = (const int*)d_in[3];
    // d_in[4] = labels (unused by the reference computation)

    cudaFuncSetAttribute(maxsim_kernel,
                         cudaFuncAttributeMaxDynamicSharedMemorySize, SMEM_BYTES);

    maxsim_kernel<<<2 * N_ * B_, NT_, SMEM_BYTES>>>(q_reps, d_cq, d_orig, d_mask);
    loss_kernel<<<1, B_>>>((float*)d_out);
}